// round 1
// baseline (speedup 1.0000x reference)
#include <cuda_runtime.h>
#include <cstdint>

// ComplexBlockLinear: out[b,s,h,{re,im}] = blockdiag complex matmul
// x: [8,4096,1024] f32 (re,im separate), weight: [8,128,128,2] f32
// Strategy: tf32 mma.sync m16n8k8, CTA = 128 rows x one 128-col block.

#define NBLK 8
#define BS 128
#define HD 1024
#define CTA_M 128
#define KC 16          // k-chunk staged in shared
#define THREADS 512    // 16 warps, 4(M) x 4(N)

// shared strides chosen conflict-free for fragment access patterns
#define XSTR 20        // 20*4c + c_off banks all distinct (20 = 4 mod 32 ... verified)
#define WSTR 136       // 136 = 8 mod 32 -> 8k+n distinct banks

__device__ __forceinline__ unsigned f2tf(float x) {
    unsigned u;
    asm("cvt.rna.tf32.f32 %0, %1;" : "=r"(u) : "f"(x));
    return u;
}

__device__ __forceinline__ void mma_tf32(float* d,
                                         const unsigned* a,
                                         unsigned b0, unsigned b1) {
    asm volatile(
        "mma.sync.aligned.m16n8k8.row.col.f32.tf32.tf32.f32 "
        "{%0,%1,%2,%3},{%4,%5,%6,%7},{%8,%9},{%0,%1,%2,%3};\n"
        : "+f"(d[0]), "+f"(d[1]), "+f"(d[2]), "+f"(d[3])
        : "r"(a[0]), "r"(a[1]), "r"(a[2]), "r"(a[3]), "r"(b0), "r"(b1));
}

__global__ __launch_bounds__(THREADS)
void cbl_tf32_kernel(const float* __restrict__ xre,
                     const float* __restrict__ xim,
                     const float* __restrict__ w,
                     float* __restrict__ out) {
    __shared__ unsigned s_xr[CTA_M][XSTR];   // only [.. ][0..KC) used
    __shared__ unsigned s_xi[CTA_M][XSTR];
    __shared__ unsigned s_wr[KC][WSTR];      // [k][o], o in 0..127
    __shared__ unsigned s_wi[KC][WSTR];

    const int tile = blockIdx.x;       // 0..255 row tile
    const int nb   = blockIdx.y;       // 0..7 block
    const int row0 = tile * CTA_M;

    const int tid  = threadIdx.x;
    const int lane = tid & 31;
    const int warp = tid >> 5;
    const int wm   = warp >> 2;        // 0..3 -> rows wm*32..+32
    const int wn   = warp & 3;         // 0..3 -> cols wn*32..+32

    float accR[2][4][4];
    float accI[2][4][4];
#pragma unroll
    for (int a = 0; a < 2; a++)
#pragma unroll
        for (int b = 0; b < 4; b++)
#pragma unroll
            for (int c = 0; c < 4; c++) { accR[a][b][c] = 0.f; accI[a][b][c] = 0.f; }

    // staging index precompute
    const int x_r  = (tid * 4) >> 4;          // 0..127
    const int x_kk = (tid * 4) & 15;          // 0,4,8,12

    for (int kc = 0; kc < BS / KC; ++kc) {
        const int k0 = kc * KC;
        __syncthreads();   // previous chunk's compute done before overwrite

        // ---- stage X chunk: 128 rows x 16 k, float4 per thread per array
        {
            const size_t goff = (size_t)(row0 + x_r) * HD + nb * BS + k0 + x_kk;
            const float4 vr = *(const float4*)(xre + goff);
            const float4 vi = *(const float4*)(xim + goff);
            uint4 tr = make_uint4(f2tf(vr.x), f2tf(vr.y), f2tf(vr.z), f2tf(vr.w));
            uint4 ti = make_uint4(f2tf(vi.x), f2tf(vi.y), f2tf(vi.z), f2tf(vi.w));
            *(uint4*)&s_xr[x_r][x_kk] = tr;
            *(uint4*)&s_xi[x_r][x_kk] = ti;
        }
        // ---- stage W chunk: 16 k x 128 o, (re,im) float2 loads
        {
#pragma unroll
            for (int t = 0; t < 4; t++) {
                const int e  = t * THREADS + tid;   // 0..2047
                const int kk = e >> 7;              // 0..15
                const int o  = e & 127;
                const float2 wv = *(const float2*)(w +
                    ((size_t)((nb * BS + k0 + kk) * BS + o)) * 2);
                s_wr[kk][o] = f2tf(wv.x);
                s_wi[kk][o] = f2tf(wv.y);
            }
        }
        __syncthreads();

        // ---- compute: 2 k-steps of 8
#pragma unroll
        for (int ks = 0; ks < KC / 8; ++ks) {
            const int kk = ks * 8;
            unsigned ar[2][4], ai[2][4];
#pragma unroll
            for (int mt = 0; mt < 2; ++mt) {
                const int rr = wm * 32 + mt * 16 + (lane >> 2);
                const int cc = kk + (lane & 3);
                ar[mt][0] = s_xr[rr][cc];
                ar[mt][1] = s_xr[rr + 8][cc];
                ar[mt][2] = s_xr[rr][cc + 4];
                ar[mt][3] = s_xr[rr + 8][cc + 4];
                ai[mt][0] = s_xi[rr][cc];
                ai[mt][1] = s_xi[rr + 8][cc];
                ai[mt][2] = s_xi[rr][cc + 4];
                ai[mt][3] = s_xi[rr + 8][cc + 4];
            }
#pragma unroll
            for (int nt = 0; nt < 4; ++nt) {
                const int n  = wn * 32 + nt * 8 + (lane >> 2);
                const int kb = kk + (lane & 3);
                const unsigned br0 = s_wr[kb][n];
                const unsigned br1 = s_wr[kb + 4][n];
                const unsigned bi0 = s_wi[kb][n];
                const unsigned bi1 = s_wi[kb + 4][n];
                const unsigned nbi0 = bi0 ^ 0x80000000u;   // -wi (tf32 sign flip)
                const unsigned nbi1 = bi1 ^ 0x80000000u;
#pragma unroll
                for (int mt = 0; mt < 2; ++mt) {
                    // out_re = xr@wr - xi@wi ; out_im = xr@wi + xi@wr
                    mma_tf32(accR[mt][nt], ar[mt], br0, br1);
                    mma_tf32(accR[mt][nt], ai[mt], nbi0, nbi1);
                    mma_tf32(accI[mt][nt], ar[mt], bi0, bi1);
                    mma_tf32(accI[mt][nt], ai[mt], br0, br1);
                }
            }
        }
    }

    // ---- epilogue: interleave (re,im) -> float4 stores, view_as_real layout
#pragma unroll
    for (int mt = 0; mt < 2; ++mt) {
        const int r_lo = row0 + wm * 32 + mt * 16 + (lane >> 2);
#pragma unroll
        for (int nt = 0; nt < 4; ++nt) {
            const int col = nb * BS + wn * 32 + nt * 8 + (lane & 3) * 2;
            float4 v0 = make_float4(accR[mt][nt][0], accI[mt][nt][0],
                                    accR[mt][nt][1], accI[mt][nt][1]);
            float4 v1 = make_float4(accR[mt][nt][2], accI[mt][nt][2],
                                    accR[mt][nt][3], accI[mt][nt][3]);
            *(float4*)(out + ((size_t)r_lo * HD + col) * 2)       = v0;
            *(float4*)(out + ((size_t)(r_lo + 8) * HD + col) * 2) = v1;
        }
    }
}

extern "C" void kernel_launch(void* const* d_in, const int* in_sizes, int n_in,
                              void* d_out, int out_size) {
    const float* xre = (const float*)d_in[0];
    const float* xim = (const float*)d_in[1];
    const float* w   = (const float*)d_in[2];
    float* out       = (float*)d_out;

    dim3 grid(32768 / CTA_M, NBLK);   // (256, 8)
    cbl_tf32_kernel<<<grid, THREADS>>>(xre, xim, w, out);
}

// round 4
// speedup vs baseline: 1.0002x; 1.0002x over previous
#include <cuda_runtime.h>
#include <cstdint>

// ComplexBlockLinear, mma.sync tf32 + cp.async double-buffered pipeline.
// x: [8,4096,1024] f32 re/im; weight [8,128,128,2]; out [8,4096,1024,2].
// CTA = 128 rows x 1 block (128 cols). 16 warps in 4(M) x 4(N); warp tile 32x32.
// K chunked by 16, raw-f32 staged via cp.async, tf32 cvt at fragment load.

#define NBLK 8
#define BS 128
#define HD 1024
#define CTA_M 128
#define KC 16
#define NCHUNK (BS / KC)     // 8
#define THREADS 512

// smem layout (floats): per stage
//   XR: 128 rows x 20 (stride 20, 16B-aligned rows)   10240 B
//   XI: same                                          10240 B
//   WW: 16 k x 264 (128 complex pairs + pad8)         16896 B
#define XSTR 20
#define WSTR 264
#define XR_OFF 0
#define XI_OFF 10240
#define WW_OFF 20480
#define STAGE_BYTES 37376
#define SMEM_TOTAL (2 * STAGE_BYTES)   // 74752

__device__ __forceinline__ uint32_t smem_u32(const void* p) {
    uint32_t a;
    asm("{ .reg .u64 t; cvta.to.shared.u64 t, %1; cvt.u32.u64 %0, t; }"
        : "=r"(a) : "l"(p));
    return a;
}
__device__ __forceinline__ unsigned f2tf(float x) {
    unsigned u;
    asm("cvt.rna.tf32.f32 %0, %1;" : "=r"(u) : "f"(x));
    return u;
}
__device__ __forceinline__ void cp16(uint32_t dst, const void* src) {
    asm volatile("cp.async.ca.shared.global [%0], [%1], 16;"
                 :: "r"(dst), "l"(src) : "memory");
}
__device__ __forceinline__ void cp_commit() {
    asm volatile("cp.async.commit_group;" ::: "memory");
}
template <int N>
__device__ __forceinline__ void cp_wait() {
    asm volatile("cp.async.wait_group %0;" :: "n"(N) : "memory");
}
__device__ __forceinline__ void mma_tf32(float* d, const unsigned* a,
                                         unsigned b0, unsigned b1) {
    asm volatile(
        "mma.sync.aligned.m16n8k8.row.col.f32.tf32.tf32.f32 "
        "{%0,%1,%2,%3},{%4,%5,%6,%7},{%8,%9},{%0,%1,%2,%3};\n"
        : "+f"(d[0]), "+f"(d[1]), "+f"(d[2]), "+f"(d[3])
        : "r"(a[0]), "r"(a[1]), "r"(a[2]), "r"(a[3]), "r"(b0), "r"(b1));
}

__global__ __launch_bounds__(THREADS)
void cbl_pipe_kernel(const float* __restrict__ xre,
                     const float* __restrict__ xim,
                     const float* __restrict__ w,
                     float* __restrict__ out) {
    extern __shared__ char smem[];
    const uint32_t sb = smem_u32(smem);

    const int tid  = threadIdx.x;
    const int lane = tid & 31;
    const int warp = tid >> 5;
    const int wm   = warp >> 2;
    const int wn   = warp & 3;

    const int row0 = blockIdx.x * CTA_M;
    const int nb   = blockIdx.y;

    // ---- staging index precompute (per thread, constant across stages)
    const int xs_r  = tid >> 2;          // 0..127
    const int xs_c  = (tid & 3) * 4;     // 0,4,8,12
    const float* xr_src0 = xre + (size_t)(row0 + xs_r) * HD + nb * BS + xs_c;
    const float* xi_src0 = xim + (size_t)(row0 + xs_r) * HD + nb * BS + xs_c;
    const uint32_t x_dst_off = xs_r * (XSTR * 4) + (tid & 3) * 16;

    float accR[2][4][4];
    float accI[2][4][4];
#pragma unroll
    for (int a = 0; a < 2; a++)
#pragma unroll
        for (int b = 0; b < 4; b++)
#pragma unroll
            for (int c = 0; c < 4; c++) { accR[a][b][c] = 0.f; accI[a][b][c] = 0.f; }

    // ---- issue one stage's cp.async group
    auto issue = [&](int c) {
        const int b = c & 1;
        const uint32_t base = sb + b * STAGE_BYTES;
        const int k0 = c * KC;
        // X: one 16B chunk per thread per array (128 rows x 16 k)
        cp16(base + XR_OFF + x_dst_off, xr_src0 + k0);
        cp16(base + XI_OFF + x_dst_off, xi_src0 + k0);
        // W: 16 k-rows x 64 chunks (each 16B = 2 complex) = 1024 chunks, 2/thread
#pragma unroll
        for (int q = 0; q < 2; ++q) {
            const int e  = q * THREADS + tid;   // 0..1023
            const int kk = e >> 6;              // 0..15
            const int oc = e & 63;              // chunk of 2 complex, 0..63
            const float* src = w +
                ((size_t)((nb * BS + k0 + kk) * BS) + oc * 2) * 2;
            cp16(base + WW_OFF + kk * (WSTR * 4) + oc * 16, src);
        }
        cp_commit();
    };

    issue(0);

#pragma unroll 1
    for (int c = 0; c < NCHUNK; ++c) {
        if (c + 1 < NCHUNK) { issue(c + 1); cp_wait<1>(); }
        else                { cp_wait<0>(); }
        __syncthreads();

        const float* sXR = (const float*)(smem + (c & 1) * STAGE_BYTES + XR_OFF);
        const float* sXI = (const float*)(smem + (c & 1) * STAGE_BYTES + XI_OFF);
        const float* sWW = (const float*)(smem + (c & 1) * STAGE_BYTES + WW_OFF);

#pragma unroll
        for (int ks = 0; ks < KC / 8; ++ks) {
            const int kk = ks * 8;
            unsigned ar[2][4], ai[2][4];
#pragma unroll
            for (int mt = 0; mt < 2; ++mt) {
                const int rr = wm * 32 + mt * 16 + (lane >> 2);
                const int cc = kk + (lane & 3);
                ar[mt][0] = f2tf(sXR[rr * XSTR + cc]);
                ar[mt][1] = f2tf(sXR[(rr + 8) * XSTR + cc]);
                ar[mt][2] = f2tf(sXR[rr * XSTR + cc + 4]);
                ar[mt][3] = f2tf(sXR[(rr + 8) * XSTR + cc + 4]);
                ai[mt][0] = f2tf(sXI[rr * XSTR + cc]);
                ai[mt][1] = f2tf(sXI[(rr + 8) * XSTR + cc]);
                ai[mt][2] = f2tf(sXI[rr * XSTR + cc + 4]);
                ai[mt][3] = f2tf(sXI[(rr + 8) * XSTR + cc + 4]);
            }
#pragma unroll
            for (int nt = 0; nt < 4; ++nt) {
                const int n  = wn * 32 + nt * 8 + (lane >> 2);
                const int kb = kk + (lane & 3);
                const float2 p0 = *(const float2*)&sWW[kb * WSTR + n * 2];
                const float2 p1 = *(const float2*)&sWW[(kb + 4) * WSTR + n * 2];
                const unsigned br0 = f2tf(p0.x);
                const unsigned bi0 = f2tf(p0.y);
                const unsigned br1 = f2tf(p1.x);
                const unsigned bi1 = f2tf(p1.y);
                const unsigned nbi0 = bi0 ^ 0x80000000u;
                const unsigned nbi1 = bi1 ^ 0x80000000u;
#pragma unroll
                for (int mt = 0; mt < 2; ++mt) {
                    mma_tf32(accR[mt][nt], ar[mt], br0, br1);
                    mma_tf32(accR[mt][nt], ai[mt], nbi0, nbi1);
                    mma_tf32(accI[mt][nt], ar[mt], bi0, bi1);
                    mma_tf32(accI[mt][nt], ai[mt], br0, br1);
                }
            }
        }
        __syncthreads();   // buffer (c&1) free for stage c+2
    }

    // ---- epilogue: interleave (re,im) -> float4 stores, view_as_real layout
#pragma unroll
    for (int mt = 0; mt < 2; ++mt) {
        const int r_lo = row0 + wm * 32 + mt * 16 + (lane >> 2);
#pragma unroll
        for (int nt = 0; nt < 4; ++nt) {
            const int col = nb * BS + wn * 32 + nt * 8 + (lane & 3) * 2;
            float4 v0 = make_float4(accR[mt][nt][0], accI[mt][nt][0],
                                    accR[mt][nt][1], accI[mt][nt][1]);
            float4 v1 = make_float4(accR[mt][nt][2], accI[mt][nt][2],
                                    accR[mt][nt][3], accI[mt][nt][3]);
            *(float4*)(out + ((size_t)r_lo * HD + col) * 2)       = v0;
            *(float4*)(out + ((size_t)(r_lo + 8) * HD + col) * 2) = v1;
        }
    }
}

extern "C" void kernel_launch(void* const* d_in, const int* in_sizes, int n_in,
                              void* d_out, int out_size) {
    const float* xre = (const float*)d_in[0];
    const float* xim = (const float*)d_in[1];
    const float* w   = (const float*)d_in[2];
    float* out       = (float*)d_out;

    cudaFuncSetAttribute(cbl_pipe_kernel,
                         cudaFuncAttributeMaxDynamicSharedMemorySize, SMEM_TOTAL);
    dim3 grid(32768 / CTA_M, NBLK);   // (256, 8)
    cbl_pipe_kernel<<<grid, THREADS, SMEM_TOTAL>>>(xre, xim, w, out);
}